// round 11
// baseline (speedup 1.0000x reference)
#include <cuda_runtime.h>
#include <cuda_fp16.h>

// ---------------------------------------------------------------------------
// VQ-VAE vector quantizer: fp16-split HMMA GEMM ranks codes (top-2 candidates),
// then an exact-fp32 refine (bitwise round-2 scalar arithmetic) decides.
//   z: [32, 64, 64, 64] fp32, emb_w: [1024, 64] fp32.
// R11: 4Mx2N warp grid (20% fewer LDSM), 1 barrier/chunk (was 2),
//      refine+gather fused into vq_finish (z staged once in smem).
// ---------------------------------------------------------------------------

#define N_TOK    131072
#define K_CODES  1024
#define D_DIM    64
#define TOK_CTA  128
#define NCTA     (N_TOK / TOK_CTA)     // 1024
#define CHUNK    64                    // codes per chunk
#define NCHUNK   (K_CODES / CHUNK)     // 16
#define KTOT     192                   // 3 x 64 split segments (hh, mh, hm)
#define KP       200                   // padded smem stride (halves); 400B rows
#define THREADS  256

#define A_SZ     (TOK_CTA * KP * 2)    // 51200 B
#define B_SZ     (CHUNK * KP * 2)      // 25600 B per buffer
#define SM_A     0
#define SM_B     A_SZ                  // two buffers
#define SM_E2    (SM_A + A_SZ + 2 * B_SZ)   // 102400
#define SMEM_TOTAL (SM_E2 + K_CODES * 4)    // 106496  -> 2 CTAs/SM

// vq_finish smem: z tile [64][260] + idx[256] + wsum[8]
#define FZS_STR  260
#define FS_SIDX  (D_DIM * FZS_STR * 4)      // 66560
#define FS_WSUM  (FS_SIDX + 256 * 4)        // 67584
#define FS_TOTAL (FS_WSUM + 64)             // 67648

typedef unsigned int u32;

__device__ __align__(16) __half g_ef[K_CODES * KTOT];  // [code][k] k-contig
__device__ float  g_e2[K_CODES];
__device__ int    g_c1[N_TOK];         // approx argmin
__device__ int    g_c2[N_TOK];         // approx runner-up
__device__ double g_loss;

// ---------------- PTX helpers ----------------------------------------------
__device__ __forceinline__ u32 smem_u32(const void* p) {
    u32 a;
    asm("{ .reg .u64 t; cvta.to.shared.u64 t, %1; cvt.u32.u64 %0, t; }" : "=r"(a) : "l"(p));
    return a;
}
#define LDSM4(r, addr)                                                                   \
    asm volatile("ldmatrix.sync.aligned.m8n8.x4.shared.b16 {%0,%1,%2,%3}, [%4];"         \
        : "=r"((r)[0]), "=r"((r)[1]), "=r"((r)[2]), "=r"((r)[3]) : "r"(addr))
#define MMA16816(d, a, b0, b1)                                                           \
    asm volatile("mma.sync.aligned.m16n8k16.row.col.f32.f16.f16.f32 "                    \
        "{%0,%1,%2,%3}, {%4,%5,%6,%7}, {%8,%9}, {%0,%1,%2,%3};"                          \
        : "+f"((d)[0]), "+f"((d)[1]), "+f"((d)[2]), "+f"((d)[3])                         \
        : "r"((a)[0]), "r"((a)[1]), "r"((a)[2]), "r"((a)[3]), "r"(b0), "r"(b1))
#define CP16(dst, src)                                                                   \
    asm volatile("cp.async.cg.shared.global [%0], [%1], 16;" :: "r"(dst), "l"(src))
#define CP_COMMIT() asm volatile("cp.async.commit_group;" ::: "memory")
#define CP_WAIT0()  asm volatile("cp.async.wait_group 0;" ::: "memory")

// lexicographic (value, index) compare: a < b ?
__device__ __forceinline__ bool vless(float av, int ai, float bv, int bi) {
    return av < bv || (av == bv && ai < bi);
}
// merge two sorted top-2 pairs
__device__ __forceinline__ void merge2(float& v1, int& i1, float& v2, int& i2,
                                       float w1, int j1, float w2, int j2) {
    if (vless(w1, j1, v1, i1)) {
        float nv2; int ni2;
        if (vless(v1, i1, w2, j2)) { nv2 = v1; ni2 = i1; } else { nv2 = w2; ni2 = j2; }
        v1 = w1; i1 = j1; v2 = nv2; i2 = ni2;
    } else if (vless(w1, j1, v2, i2)) {
        v2 = w1; i2 = j1;
    }
}

// ---------------------------------------------------------------------------
// K0: split codebook into fp16 h/m segments, compute ||e||^2, zero loss
// ---------------------------------------------------------------------------
__global__ void vq_prep(const float* __restrict__ emb) {
    int t = blockIdx.x * blockDim.x + threadIdx.x;   // 8192 threads
    if (t == 0) g_loss = 0.0;
    for (int i = t; i < K_CODES * D_DIM; i += 8192) {
        int c = i >> 6, k = i & 63;
        float v = emb[i];
        __half h = __float2half_rn(v);
        __half m = __float2half_rn(v - __half2float(h));
        g_ef[c * KTOT + k]       = h;   // pairs with z_h  -> hh
        g_ef[c * KTOT + 64 + k]  = h;   // pairs with z_m  -> mh
        g_ef[c * KTOT + 128 + k] = m;   // pairs with z_h  -> hm
    }
    if (t < K_CODES) {
        const float4* row = (const float4*)(emb + t * D_DIM);
        float s = 0.f;
#pragma unroll
        for (int i = 0; i < 16; i++) {
            float4 v = row[i];
            s += v.x * v.x + v.y * v.y + v.z * v.z + v.w * v.w;
        }
        g_e2[t] = s;
    }
}

// ---------------------------------------------------------------------------
// K1: HMMA candidate ranking. 1024 CTAs x 128 tokens. 8 warps (4M x 2N),
// warp tile 32 rows x 32 codes, chunk = 64 codes double-buffered.
// ---------------------------------------------------------------------------
__device__ __forceinline__ void issue_B(u32 sb, int buf, int chunk, int tid) {
    u32 dst0 = sb + SM_B + buf * B_SZ;
    const char* src0 = (const char*)g_ef + chunk * (CHUNK * KTOT * 2);  // dense 24576B
    for (int i = tid; i < CHUNK * 24; i += THREADS) {   // 24 x 16B segs per 384B row
        int r = i / 24, s = i - r * 24;
        CP16(dst0 + r * (KP * 2) + s * 16, src0 + i * 16);
    }
}

__global__ void __launch_bounds__(THREADS, 2) vq_argmin_mma(const float* __restrict__ z) {
    extern __shared__ char smem[];
    const u32 sb  = smem_u32(smem);
    const int tid = threadIdx.x;
    const int w   = tid >> 5, l = tid & 31;
    const int wm  = w & 3, wn = w >> 2;          // 4 M x 2 N warp grid
    const int blk = blockIdx.x;
    const int n0  = blk * TOK_CTA;

    float* e2s = (float*)(smem + SM_E2);
    for (int i = tid; i < K_CODES; i += THREADS) e2s[i] = g_e2[i];

    // ---- prologue: stage z [64][128] floats, split into A [128][192] halves
    {
        float* zst = (float*)(smem + SM_B);      // 64 x 132 floats, fits both B bufs
        const float* zsrc = z + (n0 >> 12) * (D_DIM * 4096) + (n0 & 4095);
        for (int i = tid; i < 2048; i += THREADS) {       // 64 d x 32 float4
            int d = i >> 5, g = (i & 31) << 2;
            *(float4*)(zst + d * 132 + g) = *(const float4*)(zsrc + d * 4096 + g);
        }
        __syncthreads();
        __half* As = (__half*)(smem + SM_A);
        int r = tid >> 1, d0 = (tid & 1) << 5;
#pragma unroll
        for (int j = 0; j < 32; j++) {
            int d = d0 + j;
            float v = zst[d * 132 + r];
            __half h = __float2half_rn(v);
            __half m = __float2half_rn(v - __half2float(h));
            As[r * KP + d]       = h;    // x e_h -> hh
            As[r * KP + 64 + d]  = m;    // x e_h -> mh
            As[r * KP + 128 + d] = h;    // x e_m -> hm
        }
        __syncthreads();
    }

    issue_B(sb, 0, 0, tid);
    CP_COMMIT();

    // per-thread running top-2: 2 m-tiles x 2 row-halves = 4 slots
    float v1[4], v2[4];
    int   i1[4], i2[4];
#pragma unroll
    for (int q = 0; q < 4; q++) { v1[q] = v2[q] = 3.4e38f; i1[q] = i2[q] = 0; }

    // ldmatrix lane addresses (halves): row = l&15, colgrp = (l>>4)*8
    const u32 a_lane = sb + SM_A + (u32)(((wm * 32 + (l & 15)) * KP + (l >> 4) * 8) * 2);
    const u32 b_lane_off = (u32)(((wn * 32 + (l & 15)) * KP + (l >> 4) * 8) * 2);

    for (int c = 0; c < NCHUNK; c++) {
        CP_WAIT0();
        __syncthreads();   // sole barrier: data ready + prev buffer fully consumed
        if (c < NCHUNK - 1) { issue_B(sb, (c + 1) & 1, c + 1, tid); CP_COMMIT(); }

        const u32 b_base = sb + SM_B + (u32)((c & 1) * B_SZ) + b_lane_off;

        float acc[2][2][2][4];   // mt x bl x n8 x frag
#pragma unroll
        for (int mt = 0; mt < 2; mt++)
#pragma unroll
            for (int bl = 0; bl < 2; bl++)
#pragma unroll
                for (int n8 = 0; n8 < 2; n8++)
#pragma unroll
                    for (int q = 0; q < 4; q++) acc[mt][bl][n8][q] = 0.f;

#pragma unroll
        for (int ks = 0; ks < KTOT / 16; ks++) {
            const u32 ko = ks * 32;                 // 16 halves = 32 B
            u32 af[2][4], bf[2][4];
#pragma unroll
            for (int mt = 0; mt < 2; mt++) LDSM4(af[mt], a_lane + mt * (16 * KP * 2) + ko);
#pragma unroll
            for (int bl = 0; bl < 2; bl++) LDSM4(bf[bl], b_base + bl * (16 * KP * 2) + ko);
#pragma unroll
            for (int mt = 0; mt < 2; mt++)
#pragma unroll
                for (int bl = 0; bl < 2; bl++) {
                    MMA16816(acc[mt][bl][0], af[mt], bf[bl][0], bf[bl][2]);
                    MMA16816(acc[mt][bl][1], af[mt], bf[bl][1], bf[bl][3]);
                }
        }

        // ---- scores + running top-2 (codes ascend: strict < keeps first) ---
        const int cb = c * CHUNK + wn * 32 + (l & 3) * 2;
#pragma unroll
        for (int mt = 0; mt < 2; mt++) {
#pragma unroll
            for (int bl = 0; bl < 2; bl++) {
#pragma unroll
                for (int n8 = 0; n8 < 2; n8++) {
                    int code = cb + bl * 16 + n8 * 8;
                    float2 e2p = *(const float2*)(e2s + code);
                    float s0 = fmaf(-2.f, acc[mt][bl][n8][0], e2p.x);
                    float s1 = fmaf(-2.f, acc[mt][bl][n8][1], e2p.y);
                    float s2 = fmaf(-2.f, acc[mt][bl][n8][2], e2p.x);
                    float s3 = fmaf(-2.f, acc[mt][bl][n8][3], e2p.y);
                    int q0 = mt * 2, q1 = mt * 2 + 1;
                    if (s0 < v1[q0]) { v2[q0] = v1[q0]; i2[q0] = i1[q0]; v1[q0] = s0; i1[q0] = code; }
                    else if (s0 < v2[q0]) { v2[q0] = s0; i2[q0] = code; }
                    if (s1 < v1[q0]) { v2[q0] = v1[q0]; i2[q0] = i1[q0]; v1[q0] = s1; i1[q0] = code + 1; }
                    else if (s1 < v2[q0]) { v2[q0] = s1; i2[q0] = code + 1; }
                    if (s2 < v1[q1]) { v2[q1] = v1[q1]; i2[q1] = i1[q1]; v1[q1] = s2; i1[q1] = code; }
                    else if (s2 < v2[q1]) { v2[q1] = s2; i2[q1] = code; }
                    if (s3 < v1[q1]) { v2[q1] = v1[q1]; i2[q1] = i1[q1]; v1[q1] = s3; i1[q1] = code + 1; }
                    else if (s3 < v2[q1]) { v2[q1] = s3; i2[q1] = code + 1; }
                }
            }
        }
        // no trailing barrier: next iteration's sync protects the buffer swap
    }

    // ---- reduce top-2 across quad lanes (l&3), then across 2 N-warps -------
#pragma unroll
    for (int q = 0; q < 4; q++) {
#pragma unroll
        for (int off = 1; off <= 2; off <<= 1) {
            float w1 = __shfl_xor_sync(0xffffffffu, v1[q], off);
            int   j1 = __shfl_xor_sync(0xffffffffu, i1[q], off);
            float w2 = __shfl_xor_sync(0xffffffffu, v2[q], off);
            int   j2 = __shfl_xor_sync(0xffffffffu, i2[q], off);
            merge2(v1[q], i1[q], v2[q], i2[q], w1, j1, w2, j2);
        }
    }
    float* sv1 = (float*)(smem + SM_B);          // [128][2]
    int*   si1 = (int*)(smem + SM_B + 1024);
    float* sv2 = (float*)(smem + SM_B + 2048);
    int*   si2 = (int*)(smem + SM_B + 3072);
    if ((l & 3) == 0) {
#pragma unroll
        for (int q = 0; q < 4; q++) {
            int row = wm * 32 + (q >> 1) * 16 + (q & 1) * 8 + (l >> 2);
            sv1[row * 2 + wn] = v1[q]; si1[row * 2 + wn] = i1[q];
            sv2[row * 2 + wn] = v2[q]; si2[row * 2 + wn] = i2[q];
        }
    }
    __syncthreads();
    if (tid < TOK_CTA) {
        float bv1 = sv1[tid * 2], bv2 = sv2[tid * 2];
        int   bi1 = si1[tid * 2], bi2 = si2[tid * 2];
        merge2(bv1, bi1, bv2, bi2,
               sv1[tid * 2 + 1], si1[tid * 2 + 1],
               sv2[tid * 2 + 1], si2[tid * 2 + 1]);
        g_c1[n0 + tid] = bi1;
        g_c2[n0 + tid] = bi2;
    }
}

// ---------------------------------------------------------------------------
// K2: fused refine + gather + loss. 512 blocks x 256 tokens.
// z tile staged once in smem; refine uses bitwise round-2 arithmetic.
// ---------------------------------------------------------------------------
__global__ void __launch_bounds__(256) vq_finish(const float* __restrict__ z,
                                                 const float* __restrict__ emb,
                                                 float* __restrict__ out) {
    extern __shared__ char fs[];
    float* zs   = (float*)fs;                 // [64][260]
    int*   sidx = (int*)(fs + FS_SIDX);       // [256]
    float* wsum = (float*)(fs + FS_WSUM);     // [8]
    const int tid = threadIdx.x;
    const int n0  = blockIdx.x << 8;
    const int b   = n0 >> 12, hw0 = n0 & 4095;
    const float* zb = z + b * (D_DIM * 4096) + hw0;

    for (int i = tid; i < 4096; i += 256) {   // 64 d x 64 float4
        int d = i >> 6, t4 = (i & 63) << 2;
        *(float4*)(zs + d * FZS_STR + t4) = *(const float4*)(zb + d * 4096 + t4);
    }
    __syncthreads();

    {   // refine (one token per thread) — EXACT round-2 arithmetic
        int n = n0 + tid;
        int c1 = g_c1[n], c2 = g_c2[n];
        const float* e1 = emb + c1 * D_DIM;
        const float* e2 = emb + c2 * D_DIM;
        float d1 = 0.f, d2 = 0.f;
#pragma unroll
        for (int d = 0; d < D_DIM; d++) {
            float zv = zs[d * FZS_STR + tid];
            d1 = fmaf(zv, e1[d], d1);
            d2 = fmaf(zv, e2[d], d2);
        }
        float s1 = fmaf(-2.f, d1, g_e2[c1]);
        float s2 = fmaf(-2.f, d2, g_e2[c2]);
        sidx[tid] = (s2 < s1 || (s2 == s1 && c2 < c1)) ? c2 : c1;
    }
    __syncthreads();

    float ls = 0.f;
    float* ob = out + b * (D_DIM * 4096) + hw0;
    for (int i = tid; i < 4096; i += 256) {
        int d = i >> 6, t4 = (i & 63) << 2;
        float4 zv = *(const float4*)(zs + d * FZS_STR + t4);
        int i0 = sidx[t4], i1 = sidx[t4 + 1], i2 = sidx[t4 + 2], i3 = sidx[t4 + 3];
        float q0 = emb[i0 * 64 + d];
        float q1 = emb[i1 * 64 + d];
        float q2 = emb[i2 * 64 + d];
        float q3 = emb[i3 * 64 + d];
        float t0 = q0 - zv.x, t1 = q1 - zv.y, t2 = q2 - zv.z, t3 = q3 - zv.w;
        float4 ov = { zv.x + t0, zv.y + t1, zv.z + t2, zv.w + t3 };
        *(float4*)(ob + d * 4096 + t4) = ov;
        ls += t0 * t0 + t1 * t1 + t2 * t2 + t3 * t3;
    }
#pragma unroll
    for (int off = 16; off; off >>= 1) ls += __shfl_xor_sync(0xffffffffu, ls, off);
    int lane = tid & 31, ww = tid >> 5;
    if (lane == 0) wsum[ww] = ls;
    __syncthreads();
    if (tid == 0) {
        float s = 0.f;
#pragma unroll
        for (int j = 0; j < 8; j++) s += wsum[j];
        atomicAdd(&g_loss, (double)s);
    }
}

__global__ void vq_final(float* __restrict__ out, int loc) {
    if (threadIdx.x == 0 && blockIdx.x == 0)
        out[loc] = (float)(g_loss * (1.25 / 8388608.0));
}

// ---------------------------------------------------------------------------
extern "C" void kernel_launch(void* const* d_in, const int* in_sizes, int n_in,
                              void* d_out, int out_size) {
    const float* z   = (const float*)d_in[0];
    const float* emb = (const float*)d_in[1];
    float* out = (float*)d_out;

    cudaFuncSetAttribute(vq_argmin_mma, cudaFuncAttributeMaxDynamicSharedMemorySize, SMEM_TOTAL);
    cudaFuncSetAttribute(vq_finish,     cudaFuncAttributeMaxDynamicSharedMemorySize, FS_TOTAL);

    vq_prep      <<<32, 256>>>(emb);
    vq_argmin_mma<<<NCTA, THREADS, SMEM_TOTAL>>>(z);
    vq_finish    <<<N_TOK / 256, 256, FS_TOTAL>>>(z, emb, out);
    vq_final     <<<1, 32>>>(out, out_size - 1);
}